// round 2
// baseline (speedup 1.0000x reference)
#include <cuda_runtime.h>
#include <cuda_bf16.h>
#include <math.h>
#include <stdint.h>

// ---------------- problem constants ----------------
#define BATCH 16
#define NPTS 4096
#define NCTR 1024
#define NSAMP 32
#define INDIM 64
#define D0 64
#define D1 64
#define D2 128
#define NROWS (BATCH*NCTR*NSAMP)          // 524288
#define NCTR_TOT (BATCH*NCTR)             // 16384
#define OUT_XYZ_ELEMS (NCTR_TOT*3)        // 49152

// stats layout (32 slots per channel, sum then sq)
#define SUM0 0
#define SQ0  (64*32)
#define SUM1 (2*64*32)
#define SQ1  (3*64*32)
#define SUM2 (4*64*32)
#define SQ2  (4*64*32 + 128*32)
#define STATS_TOT (4*64*32 + 2*128*32)    // 16384

// affine layout
#define A0 0
#define C0A 64
#define A1 128
#define C1A 192
#define A2 256
#define C2A 384

// ---------------- scratch (static device memory; no allocs) ----------------
__device__ int   g_fps[NCTR_TOT];
__device__ int   g_bidx[NROWS];
__device__ float g_G[BATCH*NPTS*64];      // 16 MB
__device__ float g_C[NCTR_TOT*64];        // 4 MB
__device__ float g_Y1[NROWS*64];          // 134 MB
__device__ float g_mx[NCTR_TOT*128];      // 8 MB
__device__ float g_mn[NCTR_TOT*128];      // 8 MB
__device__ float g_stats[STATS_TOT];
__device__ float g_aff[512];

__device__ __forceinline__ unsigned long long u64min(unsigned long long a, unsigned long long b){
    return a < b ? a : b;
}

// ---------------- zero stats ----------------
__global__ void zero_kernel(){
    int i = blockIdx.x*1024 + threadIdx.x;
    if (i < STATS_TOT) g_stats[i] = 0.f;
}

// ---------------- FPS: one block per batch, 256 thr, 16 pts/thread ----------------
__global__ void fps_kernel(const float* __restrict__ xyz){
    extern __shared__ float sm[];
    float* sx = sm;               // 4096
    float* sy = sm + 4096;
    float* sz = sm + 8192;
    float* sctr = sm + 12288;     // 3
    float* srd  = sm + 12292;     // 8
    int*   sri  = (int*)(sm + 12300); // 8

    int b = blockIdx.x, tid = threadIdx.x;
    const float* xb = xyz + (size_t)b*NPTS*3;

    float px[16], py[16], pz[16], dist[16];
#pragma unroll
    for (int k = 0; k < 16; k++){
        int p = k*256 + tid;
        float x = xb[p*3], y = xb[p*3+1], z = xb[p*3+2];
        px[k]=x; py[k]=y; pz[k]=z; dist[k]=INFINITY;
        sx[p]=x; sy[p]=y; sz[p]=z;
    }
    if (tid == 0) g_fps[b*NCTR] = 0;
    float cx = xb[0], cy = xb[1], cz = xb[2];
    __syncthreads();

    for (int t = 1; t < NCTR; t++){
        float bd = -1.f; int bi = 0;
#pragma unroll
        for (int k = 0; k < 16; k++){
            float dx = px[k]-cx, dy = py[k]-cy, dz = pz[k]-cz;
            float d = fmaf(dx,dx, fmaf(dy,dy, dz*dz));
            float nd = fminf(dist[k], d);
            dist[k] = nd;
            if (nd > bd){ bd = nd; bi = k*256 + tid; }
        }
        // warp reduce: max dist, tie -> smaller index (matches jnp.argmax)
#pragma unroll
        for (int off = 16; off > 0; off >>= 1){
            float od = __shfl_down_sync(0xffffffffu, bd, off);
            int   oi = __shfl_down_sync(0xffffffffu, bi, off);
            if (od > bd || (od == bd && oi < bi)){ bd = od; bi = oi; }
        }
        int w = tid >> 5;
        if ((tid & 31) == 0){ srd[w] = bd; sri[w] = bi; }
        __syncthreads();
        if (tid < 32){
            float bd2 = (tid < 8) ? srd[tid] : -1.f;
            int   bi2 = (tid < 8) ? sri[tid] : 0x7fffffff;
#pragma unroll
            for (int off = 4; off > 0; off >>= 1){
                float od = __shfl_down_sync(0xffffffffu, bd2, off);
                int   oi = __shfl_down_sync(0xffffffffu, bi2, off);
                if (od > bd2 || (od == bd2 && oi < bi2)){ bd2 = od; bi2 = oi; }
            }
            if (tid == 0){
                g_fps[b*NCTR + t] = bi2;
                sctr[0] = sx[bi2]; sctr[1] = sy[bi2]; sctr[2] = sz[bi2];
            }
        }
        __syncthreads();
        cx = sctr[0]; cy = sctr[1]; cz = sctr[2];
    }
}

// ---------------- gather new_xyz into d_out[0:49152] ----------------
__global__ void gather_kernel(const float* __restrict__ xyz, float* __restrict__ out){
    int i = blockIdx.x*256 + threadIdx.x;
    if (i >= NCTR_TOT) return;
    int b = i >> 10;
    int idx = g_fps[i];
    const float* s = xyz + ((size_t)b*NPTS + idx)*3;
    out[i*3+0] = s[0]; out[i*3+1] = s[1]; out[i*3+2] = s[2];
}

// ---------------- G = feat@W0fT + xyz@W0xT + b0 (per point) ----------------
__global__ void g_kernel(const float* __restrict__ xyz, const float* __restrict__ feat,
                         const float* __restrict__ w0, const float* __restrict__ b0){
    __shared__ float w0s[64*67];
    int tid = threadIdx.x;
    for (int i = tid; i < 64*67; i += 256) w0s[i] = w0[i];
    __syncthreads();
    int p = blockIdx.x*4 + (tid >> 6);  // global point index (b folded)
    int c = tid & 63;
    const float* fr = feat + (size_t)p*64;
    const float* wr = w0s + c*67;
    float acc = b0[c];
    acc = fmaf(xyz[p*3+0], wr[0], acc);
    acc = fmaf(xyz[p*3+1], wr[1], acc);
    acc = fmaf(xyz[p*3+2], wr[2], acc);
#pragma unroll 8
    for (int k = 0; k < 64; k++) acc = fmaf(fr[k], wr[3+k], acc);
    g_G[(size_t)p*64 + c] = acc;
}

// ---------------- C = new_xyz @ W0xT ----------------
__global__ void c_kernel(const float* __restrict__ newxyz, const float* __restrict__ w0){
    int i = blockIdx.x*256 + threadIdx.x;       // NCTR_TOT*64
    int m = i >> 6, c = i & 63;
    const float* wr = w0 + c*67;
    float acc = newxyz[m*3+0]*wr[0];
    acc = fmaf(newxyz[m*3+1], wr[1], acc);
    acc = fmaf(newxyz[m*3+2], wr[2], acc);
    g_C[i] = acc;
}

// ---------------- ball query + BN0 stats; 8 warps/block = 8 centers ----------------
__global__ void ballq_kernel(const float* __restrict__ xyz, const float* __restrict__ newxyz){
    __shared__ float sx[1024], sy[1024], sz[1024];
    __shared__ unsigned long long cbuf[8][256];
    __shared__ unsigned int usel[8][32];
    __shared__ float ssum[64], ssq[64];

    int tid = threadIdx.x, w = tid >> 5, l = tid & 31;
    int bx = blockIdx.x;
    int b = bx >> 7;                   // 128 blocks per batch
    int m = (bx & 127)*8 + w;          // center within batch
    int gm = b*NCTR + m;               // global center
    if (tid < 64){ ssum[tid] = 0.f; ssq[tid] = 0.f; }

    float qx = newxyz[gm*3], qy = newxyz[gm*3+1], qz = newxyz[gm*3+2];
    const float R2v = (float)(0.2*0.2);
    const float* xb = xyz + (size_t)b*NPTS*3;

    unsigned long long minkey = ~0ull;
    int cnt = 0;

    for (int ch = 0; ch < 4; ch++){
        __syncthreads();
        for (int i = tid; i < 1024; i += 256){
            int p = ch*1024 + i;
            sx[i] = xb[p*3]; sy[i] = xb[p*3+1]; sz[i] = xb[p*3+2];
        }
        __syncthreads();
        for (int j = 0; j < 32; j++){
            int pl = j*32 + l;
            float dx = qx - sx[pl], dy = qy - sy[pl], dz = qz - sz[pl];
            float d = fmaf(dx,dx, fmaf(dy,dy, dz*dz));
            int p = ch*1024 + pl;
            unsigned long long key = ((unsigned long long)__float_as_uint(d) << 32) | (unsigned)p;
            minkey = u64min(minkey, key);
            bool in = (d <= R2v);
            unsigned mask = __ballot_sync(0xffffffffu, in);
            if (in){
                int pos = cnt + __popc(mask & ((1u << l) - 1u));
                if (pos < 256) cbuf[w][pos] = key;
            }
            cnt += __popc(mask);
        }
    }
    // warp-reduce min key -> fill index (global argmin of (d, idx))
#pragma unroll
    for (int off = 16; off > 0; off >>= 1)
        minkey = u64min(minkey, __shfl_down_sync(0xffffffffu, minkey, off));
    minkey = __shfl_sync(0xffffffffu, minkey, 0);
    unsigned fill = (unsigned)minkey;

    if (cnt <= 32){
        unsigned v = (l < cnt) ? (unsigned)cbuf[w][l] : fill;
        usel[w][l] = v;
    } else {
        int n = cnt < 256 ? cnt : 256;
        unsigned long long e[8];
#pragma unroll
        for (int q = 0; q < 8; q++){ int p = q*32 + l; e[q] = (p < n) ? cbuf[w][p] : ~0ull; }
        for (int r = 0; r < 32; r++){
            unsigned long long loc = ~0ull;
#pragma unroll
            for (int q = 0; q < 8; q++) loc = u64min(loc, e[q]);
#pragma unroll
            for (int off = 16; off > 0; off >>= 1)
                loc = u64min(loc, __shfl_down_sync(0xffffffffu, loc, off));
            loc = __shfl_sync(0xffffffffu, loc, 0);
            if (l == r) usel[w][r] = (unsigned)loc;
#pragma unroll
            for (int q = 0; q < 8; q++) if (e[q] == loc) e[q] = ~0ull;
        }
    }
    __syncwarp();
    g_bidx[gm*32 + l] = (int)usel[w][l];

    // BN0 stats: y0 = G[idx] - C[m]; lane l handles channels l and l+32
    float Cc1 = g_C[gm*64 + l], Cc2 = g_C[gm*64 + 32 + l];
    const float* Gb = g_G + (size_t)b*NPTS*64;
    float s1 = 0.f, q1 = 0.f, s2 = 0.f, q2 = 0.f;
    for (int s = 0; s < 32; s++){
        unsigned ip = usel[w][s];
        float ga = Gb[(size_t)ip*64 + l] - Cc1;
        float gb = Gb[(size_t)ip*64 + 32 + l] - Cc2;
        s1 += ga; q1 = fmaf(ga, ga, q1);
        s2 += gb; q2 = fmaf(gb, gb, q2);
    }
    atomicAdd(&ssum[l], s1);      atomicAdd(&ssq[l], q1);
    atomicAdd(&ssum[32+l], s2);   atomicAdd(&ssq[32+l], q2);
    __syncthreads();
    if (tid < 64){
        int slot = bx & 31;
        atomicAdd(&g_stats[SUM0 + tid*32 + slot], ssum[tid]);
        atomicAdd(&g_stats[SQ0  + tid*32 + slot], ssq[tid]);
    }
}

// ---------------- BN finalize: a = gamma*rstd, c = beta - mean*a ----------------
__global__ void fin_kernel(const float* __restrict__ gamma, const float* __restrict__ beta,
                           int sumoff, int sqoff, int aoff, int coff, int nch){
    int c = threadIdx.x;
    if (c >= nch) return;
    float s = 0.f, q = 0.f;
    for (int j = 0; j < 32; j++){ s += g_stats[sumoff + c*32 + j]; q += g_stats[sqoff + c*32 + j]; }
    const float invN = 1.f / (float)NROWS;
    float mean = s * invN;
    float var = q * invN - mean*mean;
    float rstd = rsqrtf(var + 1e-5f);
    float a = gamma[c] * rstd;
    g_aff[aoff + c] = a;
    g_aff[coff + c] = beta[c] - mean * a;
}

// ---------------- layer1: 4 centers (128 rows) x 64 cols, 128 thr, 8x8 tiles ----------------
__global__ void l1_kernel(const float* __restrict__ w1, const float* __restrict__ b1){
    extern __shared__ float sm[];
    float* x1s = sm;                   // 128*65
    float* w1s = sm + 128*65;          // 64*65
    int*   sidx = (int*)(w1s + 64*65); // 128
    float* ssum = (float*)(sidx + 128);// 64
    float* ssq  = ssum + 64;           // 64

    int tid = threadIdx.x;
    int m0 = blockIdx.x * 4;
    int b = m0 >> 10;

    if (tid < 64){ ssum[tid] = 0.f; ssq[tid] = 0.f; }
    sidx[tid] = g_bidx[m0*32 + tid];
    for (int i = tid; i < 64*64; i += 128){
        int c = i >> 6, k = i & 63;
        w1s[c*65 + k] = w1[i];
    }
    __syncthreads();

    const float* Gb = g_G + (size_t)b*NPTS*64;
#pragma unroll 8
    for (int e = 0; e < 64; e++){
        int flat = e*128 + tid;
        int r = flat >> 6, c = flat & 63;
        int gm = m0 + (r >> 5);
        float y = Gb[(size_t)sidx[r]*64 + c] - g_C[gm*64 + c];
        x1s[r*65 + c] = fmaxf(fmaf(g_aff[A0 + c], y, g_aff[C0A + c]), 0.f);
    }
    __syncthreads();

    int rg = tid >> 3, cg = tid & 7;
    int rb = rg*8, cb = cg*8;
    float acc[8][8];
#pragma unroll
    for (int i = 0; i < 8; i++)
#pragma unroll
        for (int j = 0; j < 8; j++) acc[i][j] = 0.f;

#pragma unroll 4
    for (int k = 0; k < 64; k++){
        float xv[8], wv[8];
#pragma unroll
        for (int i = 0; i < 8; i++) xv[i] = x1s[(rb+i)*65 + k];
#pragma unroll
        for (int j = 0; j < 8; j++) wv[j] = w1s[(cb+j)*65 + k];
#pragma unroll
        for (int i = 0; i < 8; i++)
#pragma unroll
            for (int j = 0; j < 8; j++) acc[i][j] = fmaf(xv[i], wv[j], acc[i][j]);
    }

    float tsum[8], tsq[8];
#pragma unroll
    for (int j = 0; j < 8; j++){ tsum[j] = 0.f; tsq[j] = 0.f; }
#pragma unroll
    for (int i = 0; i < 8; i++){
        size_t R = (size_t)m0*32 + rb + i;
#pragma unroll
        for (int j = 0; j < 8; j++){
            float y = acc[i][j] + b1[cb+j];
            g_Y1[R*64 + cb + j] = y;
            tsum[j] += y; tsq[j] = fmaf(y, y, tsq[j]);
        }
    }
#pragma unroll
    for (int j = 0; j < 8; j++){
        atomicAdd(&ssum[cb+j], tsum[j]);
        atomicAdd(&ssq[cb+j], tsq[j]);
    }
    __syncthreads();
    if (tid < 64){
        int slot = blockIdx.x & 31;
        atomicAdd(&g_stats[SUM1 + tid*32 + slot], ssum[tid]);
        atomicAdd(&g_stats[SQ1  + tid*32 + slot], ssq[tid]);
    }
}

// ---------------- layer2: 2 centers (64 rows) x 128 cols, fused max/min pool ----------------
__global__ void l2_kernel(const float* __restrict__ w2, const float* __restrict__ b2){
    extern __shared__ float sm[];
    float* x2s  = sm;                  // 64*65
    float* w2s  = sm + 64*65;          // 128*65
    float* pmax = w2s + 128*65;        // 8*128
    float* pmin = pmax + 8*128;        // 8*128
    float* ssum = pmin + 8*128;        // 128
    float* ssq  = ssum + 128;          // 128

    int tid = threadIdx.x;
    int m0 = blockIdx.x * 2;

    ssum[tid] = 0.f; ssq[tid] = 0.f;
    for (int i = tid; i < 128*64; i += 128){
        int c = i >> 6, k = i & 63;
        w2s[c*65 + k] = w2[i];
    }
    for (int i = tid; i < 64*64; i += 128){
        int r = i >> 6, c = i & 63;
        float y = g_Y1[((size_t)m0*32 + r)*64 + c];
        x2s[r*65 + c] = fmaxf(fmaf(g_aff[A1 + c], y, g_aff[C1A + c]), 0.f);
    }
    __syncthreads();

    int rg = tid >> 4, cg = tid & 15;
    int rb = rg*8, cb = cg*8;
    float acc[8][8];
#pragma unroll
    for (int i = 0; i < 8; i++)
#pragma unroll
        for (int j = 0; j < 8; j++) acc[i][j] = 0.f;

#pragma unroll 4
    for (int k = 0; k < 64; k++){
        float xv[8], wv[8];
#pragma unroll
        for (int i = 0; i < 8; i++) xv[i] = x2s[(rb+i)*65 + k];
#pragma unroll
        for (int j = 0; j < 8; j++) wv[j] = w2s[(cb+j)*65 + k];
#pragma unroll
        for (int i = 0; i < 8; i++)
#pragma unroll
            for (int j = 0; j < 8; j++) acc[i][j] = fmaf(xv[i], wv[j], acc[i][j]);
    }

    float tmax[8], tmin[8], tsum[8], tsq[8];
#pragma unroll
    for (int j = 0; j < 8; j++){ tmax[j] = -INFINITY; tmin[j] = INFINITY; tsum[j] = 0.f; tsq[j] = 0.f; }
#pragma unroll
    for (int i = 0; i < 8; i++)
#pragma unroll
        for (int j = 0; j < 8; j++){
            float y = acc[i][j] + b2[cb+j];
            tmax[j] = fmaxf(tmax[j], y);
            tmin[j] = fminf(tmin[j], y);
            tsum[j] += y; tsq[j] = fmaf(y, y, tsq[j]);
        }
#pragma unroll
    for (int j = 0; j < 8; j++){
        pmax[rg*128 + cb + j] = tmax[j];
        pmin[rg*128 + cb + j] = tmin[j];
        atomicAdd(&ssum[cb+j], tsum[j]);
        atomicAdd(&ssq[cb+j], tsq[j]);
    }
    __syncthreads();

    for (int i2 = tid; i2 < 256; i2 += 128){
        int cent = i2 >> 7, c = i2 & 127;
        float mx = -INFINITY, mn = INFINITY;
#pragma unroll
        for (int r4 = 0; r4 < 4; r4++){
            mx = fmaxf(mx, pmax[(cent*4 + r4)*128 + c]);
            mn = fminf(mn, pmin[(cent*4 + r4)*128 + c]);
        }
        g_mx[(size_t)(m0+cent)*128 + c] = mx;
        g_mn[(size_t)(m0+cent)*128 + c] = mn;
    }
    int slot = blockIdx.x & 31;
    atomicAdd(&g_stats[SUM2 + tid*32 + slot], ssum[tid]);
    atomicAdd(&g_stats[SQ2  + tid*32 + slot], ssq[tid]);
}

// ---------------- final: BN2+ReLU on pooled extremum ----------------
__global__ void out_kernel(float* __restrict__ out){
    int i = blockIdx.x*256 + threadIdx.x;   // NCTR_TOT*128
    int c = i & 127;
    float a = g_aff[A2 + c];
    float v = (a >= 0.f) ? g_mx[i] : g_mn[i];
    out[OUT_XYZ_ELEMS + i] = fmaxf(fmaf(a, v, g_aff[C2A + c]), 0.f);
}

// ---------------- host launcher ----------------
extern "C" void kernel_launch(void* const* d_in, const int* in_sizes, int n_in,
                              void* d_out, int out_size){
    const float* xyz   = (const float*)d_in[0];
    const float* feat  = (const float*)d_in[1];
    const float* w0 = (const float*)d_in[2];
    const float* b0 = (const float*)d_in[3];
    const float* g0 = (const float*)d_in[4];
    const float* be0 = (const float*)d_in[5];
    const float* w1 = (const float*)d_in[6];
    const float* b1 = (const float*)d_in[7];
    const float* g1 = (const float*)d_in[8];
    const float* be1 = (const float*)d_in[9];
    const float* w2 = (const float*)d_in[10];
    const float* b2 = (const float*)d_in[11];
    const float* g2 = (const float*)d_in[12];
    const float* be2 = (const float*)d_in[13];
    float* out = (float*)d_out;

    static const int FPS_SMEM = (12288 + 3 + 8 + 8) * 4 + 64;     // ~49.3 KB
    static const int L1_SMEM  = (128*65 + 64*65 + 128 + 128) * 4; // ~51 KB
    static const int L2_SMEM  = (64*65 + 128*65 + 2*8*128 + 256) * 4; // ~59 KB
    cudaFuncSetAttribute(fps_kernel, cudaFuncAttributeMaxDynamicSharedMemorySize, FPS_SMEM);
    cudaFuncSetAttribute(l1_kernel,  cudaFuncAttributeMaxDynamicSharedMemorySize, L1_SMEM);
    cudaFuncSetAttribute(l2_kernel,  cudaFuncAttributeMaxDynamicSharedMemorySize, L2_SMEM);

    zero_kernel<<<16, 1024>>>();
    fps_kernel<<<BATCH, 256, FPS_SMEM>>>(xyz);
    gather_kernel<<<64, 256>>>(xyz, out);
    g_kernel<<<BATCH*NPTS/4, 256>>>(xyz, feat, w0, b0);
    c_kernel<<<NCTR_TOT*64/256, 256>>>(out, w0);
    ballq_kernel<<<NCTR_TOT/8, 256>>>(xyz, out);
    fin_kernel<<<1, 128>>>(g0, be0, SUM0, SQ0, A0, C0A, 64);
    l1_kernel<<<NCTR_TOT/4, 128, L1_SMEM>>>(w1, b1);
    fin_kernel<<<1, 128>>>(g1, be1, SUM1, SQ1, A1, C1A, 64);
    l2_kernel<<<NCTR_TOT/2, 128, L2_SMEM>>>(w2, b2);
    fin_kernel<<<1, 128>>>(g2, be2, SUM2, SQ2, A2, C2A, 128);
    out_kernel<<<NCTR_TOT*128/256, 256>>>(out);
}

// round 3
// speedup vs baseline: 1.0958x; 1.0958x over previous
#include <cuda_runtime.h>
#include <cuda_bf16.h>
#include <math.h>
#include <stdint.h>

// ---------------- problem constants ----------------
#define BATCH 16
#define NPTS 4096
#define NCTR 1024
#define NSAMP 32
#define INDIM 64
#define NROWS (BATCH*NCTR*NSAMP)          // 524288
#define NCTR_TOT (BATCH*NCTR)             // 16384
#define OUT_XYZ_ELEMS (NCTR_TOT*3)        // 49152
#define FPS_NB 16

// stats layout (32 slots per channel, sum then sq)
#define SUM0 0
#define SQ0  (64*32)
#define SUM1 (2*64*32)
#define SQ1  (3*64*32)
#define SUM2 (4*64*32)
#define SQ2  (4*64*32 + 128*32)
#define STATS_TOT (4*64*32 + 2*128*32)    // 16384

// affine layout
#define A0 0
#define C0A 64
#define A1 128
#define C1A 192
#define A2 256
#define C2A 384

// ---------------- scratch (static device memory; no allocs) ----------------
__device__ int   g_fps[NCTR_TOT];
__device__ int   g_bidx[NROWS];
__device__ float g_G[BATCH*NPTS*64];      // 16 MB
__device__ float g_C[NCTR_TOT*64];        // 4 MB
__device__ float g_Y1[NROWS*64];          // 134 MB
__device__ float g_mx[NCTR_TOT*128];      // 8 MB
__device__ float g_mn[NCTR_TOT*128];      // 8 MB
__device__ float g_stats[STATS_TOT];
__device__ float g_aff[512];

__device__ __forceinline__ unsigned long long u64min(unsigned long long a, unsigned long long b){
    return a < b ? a : b;
}

// =====================================================================
// MEGA kernel: blocks 0..15 = FPS (+ new_xyz gather + C) per batch;
//              blocks 16..  = G = feat@W0fT + xyz@W0xT + b0 (and stats zero)
// =====================================================================
__global__ void __launch_bounds__(256) mega_kernel(
        const float* __restrict__ xyz, const float* __restrict__ feat,
        const float* __restrict__ w0, const float* __restrict__ b0,
        float* __restrict__ out){
    extern __shared__ float sm[];
    int tid = threadIdx.x;

    if (blockIdx.x < FPS_NB){
        // ---------------- FPS branch ----------------
        float* sx = sm;               // 4096
        float* sy = sm + 4096;
        float* sz = sm + 8192;
        float (*srd)[8] = (float(*)[8])(sm + 12288);   // [2][8]
        int   (*sri)[8] = (int  (*)[8])(sm + 12288 + 16);

        int b = blockIdx.x;
        const float* xb = xyz + (size_t)b*NPTS*3;

        float px[16], py[16], pz[16], dist[16];
#pragma unroll
        for (int k = 0; k < 16; k++){
            int p = k*256 + tid;
            float x = xb[p*3], y = xb[p*3+1], z = xb[p*3+2];
            px[k]=x; py[k]=y; pz[k]=z; dist[k]=INFINITY;
            sx[p]=x; sy[p]=y; sz[p]=z;
        }
        if (tid == 0) g_fps[b*NCTR] = 0;
        float cx = xb[0], cy = xb[1], cz = xb[2];
        __syncthreads();

        int w = tid >> 5;
        for (int t = 1; t < NCTR; t++){
            float bd = -1.f; int bi = 0;
#pragma unroll
            for (int k = 0; k < 16; k++){
                float dx = px[k]-cx, dy = py[k]-cy, dz = pz[k]-cz;
                float d = fmaf(dx,dx, fmaf(dy,dy, dz*dz));
                float nd = fminf(dist[k], d);
                dist[k] = nd;
                if (nd > bd){ bd = nd; bi = k*256 + tid; }
            }
            // warp reduce: max dist, tie -> smaller global index
#pragma unroll
            for (int off = 16; off > 0; off >>= 1){
                float od = __shfl_down_sync(0xffffffffu, bd, off);
                int   oi = __shfl_down_sync(0xffffffffu, bi, off);
                if (od > bd || (od == bd && oi < bi)){ bd = od; bi = oi; }
            }
            int pb = t & 1;
            if ((tid & 31) == 0){ srd[pb][w] = bd; sri[pb][w] = bi; }
            __syncthreads();
            // every thread redundantly reduces the 8 warp partials
            float bd2 = srd[pb][0]; int bi2 = sri[pb][0];
#pragma unroll
            for (int ww = 1; ww < 8; ww++){
                float od = srd[pb][ww]; int oi = sri[pb][ww];
                if (od > bd2 || (od == bd2 && oi < bi2)){ bd2 = od; bi2 = oi; }
            }
            cx = sx[bi2]; cy = sy[bi2]; cz = sz[bi2];   // LDS broadcast
            if (tid == 0) g_fps[b*NCTR + t] = bi2;
        }
        __syncthreads();   // make g_fps writes visible to whole block

        // gather new_xyz from shared copy
        for (int i = tid; i < NCTR; i += 256){
            int idx = g_fps[b*NCTR + i];
            size_t o = (size_t)(b*NCTR + i)*3;
            out[o+0] = sx[idx]; out[o+1] = sy[idx]; out[o+2] = sz[idx];
        }
        __syncthreads();   // out visible within block

        // C = new_xyz @ W0xT for this batch
        for (int i = tid; i < NCTR*64; i += 256){
            int m = i >> 6, c = i & 63;
            const float* wr = w0 + c*67;
            size_t o = (size_t)(b*NCTR + m)*3;
            float acc = out[o+0]*wr[0];
            acc = fmaf(out[o+1], wr[1], acc);
            acc = fmaf(out[o+2], wr[2], acc);
            g_C[(size_t)(b*NCTR + m)*64 + c] = acc;
        }
    } else {
        // ---------------- G branch ----------------
        int gb = blockIdx.x - FPS_NB;
        if (gb < 16){
            for (int i = gb*1024 + tid; i < (gb+1)*1024; i += 256) g_stats[i] = 0.f;
        }
        float* w0s = sm;   // 64*67 floats
        for (int i = tid; i < 64*67; i += 256) w0s[i] = w0[i];
        __syncthreads();
        int p = gb*4 + (tid >> 6);
        int c = tid & 63;
        const float* fr = feat + (size_t)p*64;
        const float* wr = w0s + c*67;
        float acc = b0[c];
        acc = fmaf(xyz[p*3+0], wr[0], acc);
        acc = fmaf(xyz[p*3+1], wr[1], acc);
        acc = fmaf(xyz[p*3+2], wr[2], acc);
#pragma unroll 8
        for (int k = 0; k < 64; k++) acc = fmaf(fr[k], wr[3+k], acc);
        g_G[(size_t)p*64 + c] = acc;
    }
}

// ---------------- ball query + BN0 stats; 8 warps/block = 8 centers ----------------
__global__ void ballq_kernel(const float* __restrict__ xyz, const float* __restrict__ newxyz){
    __shared__ float sx[1024], sy[1024], sz[1024];
    __shared__ unsigned long long cbuf[8][256];
    __shared__ unsigned int usel[8][32];
    __shared__ float ssum[64], ssq[64];

    int tid = threadIdx.x, w = tid >> 5, l = tid & 31;
    int bx = blockIdx.x;
    int b = bx >> 7;                   // 128 blocks per batch
    int m = (bx & 127)*8 + w;          // center within batch
    int gm = b*NCTR + m;               // global center
    if (tid < 64){ ssum[tid] = 0.f; ssq[tid] = 0.f; }

    float qx = newxyz[gm*3], qy = newxyz[gm*3+1], qz = newxyz[gm*3+2];
    const float R2v = (float)(0.2*0.2);
    const float* xb = xyz + (size_t)b*NPTS*3;

    unsigned long long minkey = ~0ull;
    int cnt = 0;

    for (int ch = 0; ch < 4; ch++){
        __syncthreads();
        for (int i = tid; i < 1024; i += 256){
            int p = ch*1024 + i;
            sx[i] = xb[p*3]; sy[i] = xb[p*3+1]; sz[i] = xb[p*3+2];
        }
        __syncthreads();
        for (int j = 0; j < 32; j++){
            int pl = j*32 + l;
            float dx = qx - sx[pl], dy = qy - sy[pl], dz = qz - sz[pl];
            float d = fmaf(dx,dx, fmaf(dy,dy, dz*dz));
            int p = ch*1024 + pl;
            unsigned long long key = ((unsigned long long)__float_as_uint(d) << 32) | (unsigned)p;
            minkey = u64min(minkey, key);
            bool in = (d <= R2v);
            unsigned mask = __ballot_sync(0xffffffffu, in);
            if (in){
                int pos = cnt + __popc(mask & ((1u << l) - 1u));
                if (pos < 256) cbuf[w][pos] = key;
            }
            cnt += __popc(mask);
        }
    }
#pragma unroll
    for (int off = 16; off > 0; off >>= 1)
        minkey = u64min(minkey, __shfl_down_sync(0xffffffffu, minkey, off));
    minkey = __shfl_sync(0xffffffffu, minkey, 0);
    unsigned fill = (unsigned)minkey;

    if (cnt <= 32){
        unsigned v = (l < cnt) ? (unsigned)cbuf[w][l] : fill;
        usel[w][l] = v;
    } else {
        int n = cnt < 256 ? cnt : 256;
        unsigned long long e[8];
#pragma unroll
        for (int q = 0; q < 8; q++){ int p = q*32 + l; e[q] = (p < n) ? cbuf[w][p] : ~0ull; }
        for (int r = 0; r < 32; r++){
            unsigned long long loc = ~0ull;
#pragma unroll
            for (int q = 0; q < 8; q++) loc = u64min(loc, e[q]);
#pragma unroll
            for (int off = 16; off > 0; off >>= 1)
                loc = u64min(loc, __shfl_down_sync(0xffffffffu, loc, off));
            loc = __shfl_sync(0xffffffffu, loc, 0);
            if (l == r) usel[w][r] = (unsigned)loc;
#pragma unroll
            for (int q = 0; q < 8; q++) if (e[q] == loc) e[q] = ~0ull;
        }
    }
    __syncwarp();
    g_bidx[gm*32 + l] = (int)usel[w][l];

    // BN0 stats: y0 = G[idx] - C[m]
    float Cc1 = g_C[gm*64 + l], Cc2 = g_C[gm*64 + 32 + l];
    const float* Gb = g_G + (size_t)b*NPTS*64;
    float s1 = 0.f, q1 = 0.f, s2 = 0.f, q2 = 0.f;
    for (int s = 0; s < 32; s++){
        unsigned ip = usel[w][s];
        float ga = Gb[(size_t)ip*64 + l] - Cc1;
        float gb = Gb[(size_t)ip*64 + 32 + l] - Cc2;
        s1 += ga; q1 = fmaf(ga, ga, q1);
        s2 += gb; q2 = fmaf(gb, gb, q2);
    }
    atomicAdd(&ssum[l], s1);      atomicAdd(&ssq[l], q1);
    atomicAdd(&ssum[32+l], s2);   atomicAdd(&ssq[32+l], q2);
    __syncthreads();
    if (tid < 64){
        int slot = bx & 31;
        atomicAdd(&g_stats[SUM0 + tid*32 + slot], ssum[tid]);
        atomicAdd(&g_stats[SQ0  + tid*32 + slot], ssq[tid]);
    }
}

// ---------------- BN finalize ----------------
__global__ void fin_kernel(const float* __restrict__ gamma, const float* __restrict__ beta,
                           int sumoff, int sqoff, int aoff, int coff, int nch){
    int c = threadIdx.x;
    if (c >= nch) return;
    float s = 0.f, q = 0.f;
    for (int j = 0; j < 32; j++){ s += g_stats[sumoff + c*32 + j]; q += g_stats[sqoff + c*32 + j]; }
    const float invN = 1.f / (float)NROWS;
    float mean = s * invN;
    float var = q * invN - mean*mean;
    float rstd = rsqrtf(var + 1e-5f);
    float a = gamma[c] * rstd;
    g_aff[aoff + c] = a;
    g_aff[coff + c] = beta[c] - mean * a;
}

// ---------------- layer1 ----------------
__global__ void l1_kernel(const float* __restrict__ w1, const float* __restrict__ b1){
    extern __shared__ float sm[];
    float* x1s = sm;                   // 128*65
    float* w1s = sm + 128*65;          // 64*65
    int*   sidx = (int*)(w1s + 64*65); // 128
    float* ssum = (float*)(sidx + 128);// 64
    float* ssq  = ssum + 64;           // 64

    int tid = threadIdx.x;
    int m0 = blockIdx.x * 4;
    int b = m0 >> 10;

    if (tid < 64){ ssum[tid] = 0.f; ssq[tid] = 0.f; }
    sidx[tid] = g_bidx[m0*32 + tid];
    for (int i = tid; i < 64*64; i += 128){
        int c = i >> 6, k = i & 63;
        w1s[c*65 + k] = w1[i];
    }
    __syncthreads();

    const float* Gb = g_G + (size_t)b*NPTS*64;
#pragma unroll 8
    for (int e = 0; e < 64; e++){
        int flat = e*128 + tid;
        int r = flat >> 6, c = flat & 63;
        int gm = m0 + (r >> 5);
        float y = Gb[(size_t)sidx[r]*64 + c] - g_C[gm*64 + c];
        x1s[r*65 + c] = fmaxf(fmaf(g_aff[A0 + c], y, g_aff[C0A + c]), 0.f);
    }
    __syncthreads();

    int rg = tid >> 3, cg = tid & 7;
    int rb = rg*8, cb = cg*8;
    float acc[8][8];
#pragma unroll
    for (int i = 0; i < 8; i++)
#pragma unroll
        for (int j = 0; j < 8; j++) acc[i][j] = 0.f;

#pragma unroll 4
    for (int k = 0; k < 64; k++){
        float xv[8], wv[8];
#pragma unroll
        for (int i = 0; i < 8; i++) xv[i] = x1s[(rb+i)*65 + k];
#pragma unroll
        for (int j = 0; j < 8; j++) wv[j] = w1s[(cb+j)*65 + k];
#pragma unroll
        for (int i = 0; i < 8; i++)
#pragma unroll
            for (int j = 0; j < 8; j++) acc[i][j] = fmaf(xv[i], wv[j], acc[i][j]);
    }

    float tsum[8], tsq[8];
#pragma unroll
    for (int j = 0; j < 8; j++){ tsum[j] = 0.f; tsq[j] = 0.f; }
#pragma unroll
    for (int i = 0; i < 8; i++){
        size_t R = (size_t)m0*32 + rb + i;
#pragma unroll
        for (int j = 0; j < 8; j++){
            float y = acc[i][j] + b1[cb+j];
            g_Y1[R*64 + cb + j] = y;
            tsum[j] += y; tsq[j] = fmaf(y, y, tsq[j]);
        }
    }
#pragma unroll
    for (int j = 0; j < 8; j++){
        atomicAdd(&ssum[cb+j], tsum[j]);
        atomicAdd(&ssq[cb+j], tsq[j]);
    }
    __syncthreads();
    if (tid < 64){
        int slot = blockIdx.x & 31;
        atomicAdd(&g_stats[SUM1 + tid*32 + slot], ssum[tid]);
        atomicAdd(&g_stats[SQ1  + tid*32 + slot], ssq[tid]);
    }
}

// ---------------- layer2 + fused max/min pool ----------------
__global__ void l2_kernel(const float* __restrict__ w2, const float* __restrict__ b2){
    extern __shared__ float sm[];
    float* x2s  = sm;                  // 64*65
    float* w2s  = sm + 64*65;          // 128*65
    float* pmax = w2s + 128*65;        // 8*128
    float* pmin = pmax + 8*128;        // 8*128
    float* ssum = pmin + 8*128;        // 128
    float* ssq  = ssum + 128;          // 128

    int tid = threadIdx.x;
    int m0 = blockIdx.x * 2;

    ssum[tid] = 0.f; ssq[tid] = 0.f;
    for (int i = tid; i < 128*64; i += 128){
        int c = i >> 6, k = i & 63;
        w2s[c*65 + k] = w2[i];
    }
    for (int i = tid; i < 64*64; i += 128){
        int r = i >> 6, c = i & 63;
        float y = g_Y1[((size_t)m0*32 + r)*64 + c];
        x2s[r*65 + c] = fmaxf(fmaf(g_aff[A1 + c], y, g_aff[C1A + c]), 0.f);
    }
    __syncthreads();

    int rg = tid >> 4, cg = tid & 15;
    int rb = rg*8, cb = cg*8;
    float acc[8][8];
#pragma unroll
    for (int i = 0; i < 8; i++)
#pragma unroll
        for (int j = 0; j < 8; j++) acc[i][j] = 0.f;

#pragma unroll 4
    for (int k = 0; k < 64; k++){
        float xv[8], wv[8];
#pragma unroll
        for (int i = 0; i < 8; i++) xv[i] = x2s[(rb+i)*65 + k];
#pragma unroll
        for (int j = 0; j < 8; j++) wv[j] = w2s[(cb+j)*65 + k];
#pragma unroll
        for (int i = 0; i < 8; i++)
#pragma unroll
            for (int j = 0; j < 8; j++) acc[i][j] = fmaf(xv[i], wv[j], acc[i][j]);
    }

    float tmax[8], tmin[8], tsum[8], tsq[8];
#pragma unroll
    for (int j = 0; j < 8; j++){ tmax[j] = -INFINITY; tmin[j] = INFINITY; tsum[j] = 0.f; tsq[j] = 0.f; }
#pragma unroll
    for (int i = 0; i < 8; i++)
#pragma unroll
        for (int j = 0; j < 8; j++){
            float y = acc[i][j] + b2[cb+j];
            tmax[j] = fmaxf(tmax[j], y);
            tmin[j] = fminf(tmin[j], y);
            tsum[j] += y; tsq[j] = fmaf(y, y, tsq[j]);
        }
#pragma unroll
    for (int j = 0; j < 8; j++){
        pmax[rg*128 + cb + j] = tmax[j];
        pmin[rg*128 + cb + j] = tmin[j];
        atomicAdd(&ssum[cb+j], tsum[j]);
        atomicAdd(&ssq[cb+j], tsq[j]);
    }
    __syncthreads();

    for (int i2 = tid; i2 < 256; i2 += 128){
        int cent = i2 >> 7, c = i2 & 127;
        float mx = -INFINITY, mn = INFINITY;
#pragma unroll
        for (int r4 = 0; r4 < 4; r4++){
            mx = fmaxf(mx, pmax[(cent*4 + r4)*128 + c]);
            mn = fminf(mn, pmin[(cent*4 + r4)*128 + c]);
        }
        g_mx[(size_t)(m0+cent)*128 + c] = mx;
        g_mn[(size_t)(m0+cent)*128 + c] = mn;
    }
    int slot = blockIdx.x & 31;
    atomicAdd(&g_stats[SUM2 + tid*32 + slot], ssum[tid]);
    atomicAdd(&g_stats[SQ2  + tid*32 + slot], ssq[tid]);
}

// ---------------- final: BN2+ReLU on pooled extremum ----------------
__global__ void out_kernel(float* __restrict__ out){
    int i = blockIdx.x*256 + threadIdx.x;   // NCTR_TOT*128
    int c = i & 127;
    float a = g_aff[A2 + c];
    float v = (a >= 0.f) ? g_mx[i] : g_mn[i];
    out[OUT_XYZ_ELEMS + i] = fmaxf(fmaf(a, v, g_aff[C2A + c]), 0.f);
}

// ---------------- host launcher ----------------
extern "C" void kernel_launch(void* const* d_in, const int* in_sizes, int n_in,
                              void* d_out, int out_size){
    const float* xyz   = (const float*)d_in[0];
    const float* feat  = (const float*)d_in[1];
    const float* w0 = (const float*)d_in[2];
    const float* b0 = (const float*)d_in[3];
    const float* g0 = (const float*)d_in[4];
    const float* be0 = (const float*)d_in[5];
    const float* w1 = (const float*)d_in[6];
    const float* b1 = (const float*)d_in[7];
    const float* g1 = (const float*)d_in[8];
    const float* be1 = (const float*)d_in[9];
    const float* w2 = (const float*)d_in[10];
    const float* b2 = (const float*)d_in[11];
    const float* g2 = (const float*)d_in[12];
    const float* be2 = (const float*)d_in[13];
    float* out = (float*)d_out;

    static const int MEGA_SMEM = (12288 + 64) * 4;                 // ~49.4 KB
    static const int L1_SMEM  = (128*65 + 64*65 + 128 + 128) * 4;  // ~51 KB
    static const int L2_SMEM  = (64*65 + 128*65 + 2*8*128 + 256) * 4; // ~59 KB
    cudaFuncSetAttribute(mega_kernel, cudaFuncAttributeMaxDynamicSharedMemorySize, MEGA_SMEM);
    cudaFuncSetAttribute(l1_kernel,  cudaFuncAttributeMaxDynamicSharedMemorySize, L1_SMEM);
    cudaFuncSetAttribute(l2_kernel,  cudaFuncAttributeMaxDynamicSharedMemorySize, L2_SMEM);

    mega_kernel<<<FPS_NB + BATCH*NPTS/4, 256, MEGA_SMEM>>>(xyz, feat, w0, b0, out);
    ballq_kernel<<<NCTR_TOT/8, 256>>>(xyz, out);
    fin_kernel<<<1, 128>>>(g0, be0, SUM0, SQ0, A0, C0A, 64);
    l1_kernel<<<NCTR_TOT/4, 128, L1_SMEM>>>(w1, b1);
    fin_kernel<<<1, 128>>>(g1, be1, SUM1, SQ1, A1, C1A, 64);
    l2_kernel<<<NCTR_TOT/2, 128, L2_SMEM>>>(w2, b2);
    fin_kernel<<<1, 128>>>(g2, be2, SUM2, SQ2, A2, C2A, 128);
    out_kernel<<<NCTR_TOT*128/256, 256>>>(out);
}